// round 16
// baseline (speedup 1.0000x reference)
#include <cuda_runtime.h>
#include <cuda_bf16.h>
#include <cooperative_groups.h>
#include <math.h>
#include <stdint.h>

namespace cg = cooperative_groups;

#define BSZ   8
#define LSEQ  2048
#define DMOD  1024
#define SDIM  256
#define MROWS (BSZ*LSEQ)   // 16384

// ---------------------------------------------------------------------------
// Static device scratch
// ---------------------------------------------------------------------------
__device__ __align__(128) __nv_bfloat16 g_wh[2][(size_t)MROWS * SDIM];
__device__ __align__(128) __nv_bfloat16 g_wl[2][(size_t)MROWS * SDIM];
__device__ __align__(128) __nv_bfloat16 g_Bh[SDIM * DMOD];
__device__ __align__(128) __nv_bfloat16 g_Bl[SDIM * DMOD];
__device__ __align__(128) __nv_bfloat16 g_Ch[DMOD * SDIM];
__device__ __align__(128) __nv_bfloat16 g_Cl[DMOD * SDIM];
__device__ __align__(128) float         g_P[2][SDIM * SDIM];      // A^2, A^4 fp32
__device__ __align__(128) __nv_bfloat16 g_Ph[SDIM * SDIM];        // A hi (d=1)
__device__ __align__(128) __nv_bfloat16 g_Pl[SDIM * SDIM];        // A lo (d=1)
__device__ __align__(128) __nv_bfloat16 g_P2h[2][SDIM * SDIM];    // A^2, A^4 hi

// ---------------------------------------------------------------------------
// Side stream + fork/join events (created once at static init).
// ---------------------------------------------------------------------------
struct SideStream {
    cudaStream_t s2;
    cudaEvent_t  eFork, eJoin;
    SideStream() {
        cudaStreamCreateWithFlags(&s2, cudaStreamNonBlocking);
        cudaEventCreateWithFlags(&eFork, cudaEventDisableTiming);
        cudaEventCreateWithFlags(&eJoin, cudaEventDisableTiming);
    }
};
static SideStream g_ss;

// ---------------------------------------------------------------------------
// PTX helpers (base sm_80+ ISA only)
// ---------------------------------------------------------------------------
__device__ __forceinline__ uint32_t smem_u32(const void* p) {
    uint32_t a;
    asm("{ .reg .u64 t; cvta.to.shared.u64 t, %1; cvt.u32.u64 %0, t; }" : "=r"(a) : "l"(p));
    return a;
}
__device__ __forceinline__ void cp16(uint32_t s, const void* g) {
    asm volatile("cp.async.cg.shared.global [%0], [%1], 16;" :: "r"(s), "l"(g));
}
__device__ __forceinline__ void cp16z(uint32_t s, const void* g, int sz) {
    asm volatile("cp.async.cg.shared.global [%0], [%1], 16, %2;" :: "r"(s), "l"(g), "r"(sz));
}
#define CP_COMMIT()   asm volatile("cp.async.commit_group;" ::: "memory")
#define CP_WAIT0()    asm volatile("cp.async.wait_group 0;" ::: "memory")

__device__ __forceinline__ void ldm_x4(uint32_t* r, uint32_t saddr) {
    asm volatile("ldmatrix.sync.aligned.m8n8.x4.shared.b16 {%0,%1,%2,%3}, [%4];"
        : "=r"(r[0]), "=r"(r[1]), "=r"(r[2]), "=r"(r[3]) : "r"(saddr));
}
__device__ __forceinline__ void mma16816(float* c, const uint32_t* a, const uint32_t* b) {
    asm volatile("mma.sync.aligned.m16n8k16.row.col.f32.bf16.bf16.f32 "
        "{%0,%1,%2,%3}, {%4,%5,%6,%7}, {%8,%9}, {%0,%1,%2,%3};"
        : "+f"(c[0]), "+f"(c[1]), "+f"(c[2]), "+f"(c[3])
        : "r"(a[0]), "r"(a[1]), "r"(a[2]), "r"(a[3]), "r"(b[0]), "r"(b[1]));
}

__device__ __forceinline__ float gelu_exact(float x) {
    return 0.5f * x * (1.0f + erff(x * 0.7071067811865476f));
}
__device__ __forceinline__ void split_bf(float v, __nv_bfloat16& h, __nv_bfloat16& l) {
    h = __float2bfloat16(v);
    l = __float2bfloat16(v - __bfloat162float(h));
}
__device__ __forceinline__ void pack_split4(float4 v, uint2& hv, uint2& lv) {
    __nv_bfloat16 h0, h1, h2, h3, l0, l1, l2, l3;
    split_bf(v.x, h0, l0); split_bf(v.y, h1, l1);
    split_bf(v.z, h2, l2); split_bf(v.w, h3, l3);
    hv.x = (uint32_t)__bfloat16_as_ushort(h0) | ((uint32_t)__bfloat16_as_ushort(h1) << 16);
    hv.y = (uint32_t)__bfloat16_as_ushort(h2) | ((uint32_t)__bfloat16_as_ushort(h3) << 16);
    lv.x = (uint32_t)__bfloat16_as_ushort(l0) | ((uint32_t)__bfloat16_as_ushort(l1) << 16);
    lv.y = (uint32_t)__bfloat16_as_ushort(l2) | ((uint32_t)__bfloat16_as_ushort(l3) << 16);
}
__device__ __forceinline__ uint2 pack_hi4(float4 v) {
    uint2 hv;
    hv.x = (uint32_t)__bfloat16_as_ushort(__float2bfloat16(v.x))
         | ((uint32_t)__bfloat16_as_ushort(__float2bfloat16(v.y)) << 16);
    hv.y = (uint32_t)__bfloat16_as_ushort(__float2bfloat16(v.z))
         | ((uint32_t)__bfloat16_as_ushort(__float2bfloat16(v.w)) << 16);
    return hv;
}

// ---------------------------------------------------------------------------
// bsplit / prep2 / conv_hi / matsq_sk
// ---------------------------------------------------------------------------
__global__ void bsplit(const float* __restrict__ Bm,
                       __nv_bfloat16* __restrict__ Bh, __nv_bfloat16* __restrict__ Bl) {
    int i = blockIdx.x * blockDim.x + threadIdx.x;
    if (i >= SDIM * DMOD / 4) return;
    float4 v = ((const float4*)Bm)[i];
    uint2 hv, lv;
    pack_split4(v, hv, lv);
    ((uint2*)Bh)[i] = hv;
    ((uint2*)Bl)[i] = lv;
}

__global__ void prep2(const float* __restrict__ C, const float* __restrict__ A,
                      __nv_bfloat16* __restrict__ Ch, __nv_bfloat16* __restrict__ Cl,
                      __nv_bfloat16* __restrict__ Ph, __nv_bfloat16* __restrict__ Pl,
                      float* __restrict__ P) {
    const int nC = DMOD * SDIM / 4, nA = SDIM * SDIM / 4;
    const int nZ = 2 * SDIM * SDIM / 4;
    int i = blockIdx.x * blockDim.x + threadIdx.x;
    const float* src; __nv_bfloat16 *h, *l; int j;
    if (i < nC)           { src = C; h = Ch; l = Cl; j = i; }
    else if (i < nC + nA) { src = A; h = Ph; l = Pl; j = i - nC; }
    else if (i < nC + nA + nZ) {
        ((float4*)P)[i - nC - nA] = make_float4(0.f, 0.f, 0.f, 0.f);
        return;
    } else return;
    float4 v = ((const float4*)src)[j];
    uint2 hv, lv;
    pack_split4(v, hv, lv);
    ((uint2*)h)[j] = hv;
    ((uint2*)l)[j] = lv;
}

__global__ void conv_hi(const float* __restrict__ in,
                        __nv_bfloat16* __restrict__ h, int n4) {
    int i = blockIdx.x * blockDim.x + threadIdx.x;
    if (i >= n4) return;
    ((uint2*)h)[i] = pack_hi4(((const float4*)in)[i]);
}

__global__ __launch_bounds__(256) void matsq_sk(const float* __restrict__ In,
                                                float* __restrict__ Out) {
    __shared__ float sA[64][33];
    __shared__ float sB[32][65];
    const int tid = threadIdx.x;
    const int i0 = blockIdx.y * 64, j0 = blockIdx.x * 64, k0 = blockIdx.z * 32;
#pragma unroll
    for (int i = 0; i < 8; i++) {
        int e = tid + i * 256;
        int ar = e >> 5, ak = e & 31;
        sA[ar][ak] = In[(i0 + ar) * SDIM + k0 + ak];
        int br = e >> 6, bc = e & 63;
        sB[br][bc] = In[(k0 + br) * SDIM + j0 + bc];
    }
    __syncthreads();
    const int ty = tid >> 4, tx = tid & 15;
    float acc[4][4] = {};
#pragma unroll
    for (int k = 0; k < 32; k++) {
        float a[4], b[4];
#pragma unroll
        for (int q = 0; q < 4; q++) a[q] = sA[ty * 4 + q][k];
#pragma unroll
        for (int q = 0; q < 4; q++) b[q] = sB[k][tx * 4 + q];
#pragma unroll
        for (int q = 0; q < 4; q++)
#pragma unroll
            for (int r = 0; r < 4; r++) acc[q][r] = fmaf(a[q], b[r], acc[q][r]);
    }
#pragma unroll
    for (int q = 0; q < 4; q++)
#pragma unroll
        for (int r = 0; r < 4; r++)
            atomicAdd(&Out[(i0 + ty * 4 + q) * SDIM + j0 + tx * 4 + r], acc[q][r]);
}

// ---------------------------------------------------------------------------
// GEMM1 (unchanged, at floor): C[128 x 256] = x[M,K] @ B[N,K]^T, 512 threads.
// ---------------------------------------------------------------------------
#define BKQ      64
#define LROW     144
#define A_H_OFF  0
#define A_L_OFF  18432
#define B_H_OFF  36864
#define B_L_OFF  73728
#define STAGE_B  110592
#define SMEM_SZ  (2 * STAGE_B)
#define LDCE     260
#define NTHR     512

__global__ __launch_bounds__(NTHR, 1) void gemm1(
    const float* __restrict__ Xf,
    const __nv_bfloat16* __restrict__ Bh, const __nv_bfloat16* __restrict__ Bl,
    __nv_bfloat16* __restrict__ outh, __nv_bfloat16* __restrict__ outl,
    int K)
{
    extern __shared__ char smem[];
    const int tid = threadIdx.x;
    const int bm = blockIdx.y * 128;
    const int nb = 0;
    const int NC = K / BKQ;
    const uint32_t sb = smem_u32(smem);

    const int w    = tid >> 5;
    const int lane = tid & 31;
    const int wm = w & 3;
    const int wn = w >> 2;

    const int lt = lane >> 3, lr = lane & 7;
    const uint32_t aLane = (uint32_t)(((lt & 1) * 8 + lr) * LROW + (lt >> 1) * 16);
    const uint32_t bLane = (uint32_t)(((lt >> 1) * 8 + lr) * LROW + (lt & 1) * 16);

    float acc[2][8][4];
#pragma unroll
    for (int i = 0; i < 2; i++)
#pragma unroll
        for (int j = 0; j < 8; j++)
#pragma unroll
            for (int q = 0; q < 4; q++) acc[i][j][q] = 0.f;

    float4 xr[4];

    auto ldregs = [&](int c) {
        const int k0 = c * BKQ;
#pragma unroll
        for (int i = 0; i < 4; i++) {
            int e = tid + i * NTHR;
            int row = e >> 4, cgp = e & 15;
            xr[i] = *(const float4*)(Xf + (size_t)(bm + row) * K + k0 + cgp * 4);
        }
    };
    auto st_A = [&](int buf) {
        char* base = smem + buf * STAGE_B;
#pragma unroll
        for (int i = 0; i < 4; i++) {
            int e = tid + i * NTHR;
            int row = e >> 4, cgp = e & 15;
            uint2 hv, lv;
            pack_split4(xr[i], hv, lv);
            uint32_t so = row * LROW + cgp * 8;
            *(uint2*)(base + A_H_OFF + so) = hv;
            *(uint2*)(base + A_L_OFF + so) = lv;
        }
    };
    auto issueB = [&](int c, int buf) {
        const uint32_t base = sb + buf * STAGE_B;
        const int k0 = c * BKQ;
#pragma unroll
        for (int i = 0; i < 4; i++) {
            int e = tid + i * NTHR;
            int row = e >> 3, kc = e & 7;
            size_t go = (size_t)(nb + row) * K + k0 + kc * 8;
            uint32_t so = base + row * LROW + kc * 16;
            cp16(so + B_H_OFF, Bh + go);
            cp16(so + B_L_OFF, Bl + go);
        }
    };
    auto compute = [&](int b) {
        const uint32_t aBase = sb + b * STAGE_B + A_H_OFF + (wm * 32) * LROW + aLane;
        const uint32_t bBase = sb + b * STAGE_B + B_H_OFF + (wn * 64) * LROW + bLane;
#pragma unroll
        for (int kk = 0; kk < 4; kk++) {
            uint32_t ah[2][4], al[2][4];
#pragma unroll
            for (int mi = 0; mi < 2; mi++) {
                uint32_t a0 = aBase + mi * (16 * LROW) + kk * 32;
                ldm_x4(ah[mi], a0);
                ldm_x4(al[mi], a0 + (A_L_OFF - A_H_OFF));
            }
#pragma unroll
            for (int g = 0; g < 4; g++) {
                uint32_t bh[4], bl[4];
                uint32_t b0 = bBase + g * (16 * LROW) + kk * 32;
                ldm_x4(bh, b0);
                ldm_x4(bl, b0 + (B_L_OFF - B_H_OFF));
#pragma unroll
                for (int mi = 0; mi < 2; mi++) {
                    mma16816(acc[mi][2 * g],     ah[mi], bh);
                    mma16816(acc[mi][2 * g],     ah[mi], bl);
                    mma16816(acc[mi][2 * g],     al[mi], bh);
                    mma16816(acc[mi][2 * g + 1], ah[mi], bh + 2);
                    mma16816(acc[mi][2 * g + 1], ah[mi], bl + 2);
                    mma16816(acc[mi][2 * g + 1], al[mi], bh + 2);
                }
            }
        }
    };

    ldregs(0); st_A(0);
    issueB(0, 0);
    CP_COMMIT();

    for (int c = 0; c < NC; c++) {
        const int b = c & 1;
        const bool more = (c + 1 < NC);
        if (more) ldregs(c + 1);
        CP_WAIT0();
        __syncthreads();
        if (more) { issueB(c + 1, b ^ 1); CP_COMMIT(); }
        compute(b);
        if (more) st_A(b ^ 1);
    }
    __syncthreads();

    float* Cs = (float*)smem;
    const int g4 = lane >> 2, tig = lane & 3;
#pragma unroll
    for (int mi = 0; mi < 2; mi++)
#pragma unroll
        for (int nj = 0; nj < 8; nj++) {
            int row = wm * 32 + mi * 16 + g4;
            int col = wn * 64 + nj * 8 + tig * 2;
            *(float2*)(Cs + row * LDCE + col)       = make_float2(acc[mi][nj][0], acc[mi][nj][1]);
            *(float2*)(Cs + (row + 8) * LDCE + col) = make_float2(acc[mi][nj][2], acc[mi][nj][3]);
        }
    __syncthreads();

    const int r = tid >> 2;
    const int ch = (tid & 3) * 64;
    const int gr = bm + r;
    const float* crow = Cs + r * LDCE + ch;

#pragma unroll
    for (int g = 0; g < 8; g++) {
        float v[8];
#pragma unroll
        for (int q = 0; q < 8; q++) v[q] = crow[g * 8 + q];
        size_t gcol = (size_t)gr * SDIM + ch + g * 8;
        __nv_bfloat16 hv[8], lv[8];
#pragma unroll
        for (int q = 0; q < 8; q++) split_bf(v[q], hv[q], lv[q]);
        *(uint4*)(outh + gcol) = *(const uint4*)hv;
        *(uint4*)(outl + gcol) = *(const uint4*)lv;
    }
}

// ---------------------------------------------------------------------------
// scan1: d=1 stage, BM=64, single-buffered smem, occupancy 2, 3-term split.
//   out = (wh+wl) + shift(wh/wl, 1) @ A^T
// smem: A h/l (2*9216) + B h/l (2*36864) = 92160.
// ---------------------------------------------------------------------------
#define S1_AH    0
#define S1_AL    9216
#define S1_BH    18432
#define S1_BL    55296
#define S1_SMEM  92160

__global__ __launch_bounds__(256, 2) void scan1(
    const __nv_bfloat16* __restrict__ Wh, const __nv_bfloat16* __restrict__ Wl,
    const __nv_bfloat16* __restrict__ Ph, const __nv_bfloat16* __restrict__ Pl,
    __nv_bfloat16* __restrict__ outh, __nv_bfloat16* __restrict__ outl)
{
    extern __shared__ char smem[];
    const int tid = threadIdx.x;
    const int bm = blockIdx.y * 64;
    const uint32_t sb = smem_u32(smem);

    const int w    = tid >> 5;
    const int lane = tid & 31;
    const int wm = w & 1;
    const int wn = w >> 1;
    const int lt = lane >> 3, lr = lane & 7;
    const uint32_t aLane = (uint32_t)(((lt & 1) * 8 + lr) * LROW + (lt >> 1) * 16);
    const uint32_t bLane = (uint32_t)(((lt >> 1) * 8 + lr) * LROW + (lt & 1) * 16);

    float acc[2][8][4];
#pragma unroll
    for (int i = 0; i < 2; i++)
#pragma unroll
        for (int j = 0; j < 8; j++)
#pragma unroll
            for (int q = 0; q < 4; q++) acc[i][j][q] = 0.f;

    for (int c = 0; c < 4; c++) {
        const int k0 = c * BKQ;
        // A: 64 rows, shifted by 1 (zero-fill at sequence start), h/l
#pragma unroll
        for (int i = 0; i < 2; i++) {
            int e = tid + i * 256;
            int row = e >> 3, kc = e & 7;
            int gr = bm + row;
            int t = gr & (LSEQ - 1);
            int sz = (t >= 1) ? 16 : 0;
            int srow = gr - (t >= 1 ? 1 : 0);
            size_t go = (size_t)srow * SDIM + k0 + kc * 8;
            uint32_t so = sb + row * LROW + kc * 16;
            cp16z(so + S1_AH, Wh + go, sz);
            cp16z(so + S1_AL, Wl + go, sz);
        }
        // B: 256 rows of A (the state matrix), h/l
#pragma unroll
        for (int i = 0; i < 8; i++) {
            int e = tid + i * 256;
            int row = e >> 3, kc = e & 7;
            size_t go = (size_t)row * SDIM + k0 + kc * 8;
            uint32_t so = sb + row * LROW + kc * 16;
            cp16(so + S1_BH, Ph + go);
            cp16(so + S1_BL, Pl + go);
        }
        CP_COMMIT();
        CP_WAIT0();
        __syncthreads();

        const uint32_t aBase = sb + S1_AH + (wm * 32) * LROW + aLane;
        const uint32_t bBase = sb + S1_BH + (wn * 64) * LROW + bLane;
#pragma unroll
        for (int kk = 0; kk < 4; kk++) {
            uint32_t ah[2][4], al[2][4];
#pragma unroll
            for (int mi = 0; mi < 2; mi++) {
                uint32_t a0 = aBase + mi * (16 * LROW) + kk * 32;
                ldm_x4(ah[mi], a0);
                ldm_x4(al[mi], a0 + (S1_AL - S1_AH));
            }
#pragma unroll
            for (int g = 0; g < 4; g++) {
                uint32_t bh[4], bl[4];
                uint32_t b0 = bBase + g * (16 * LROW) + kk * 32;
                ldm_x4(bh, b0);
                ldm_x4(bl, b0 + (S1_BL - S1_BH));
#pragma unroll
                for (int mi = 0; mi < 2; mi++) {
                    mma16816(acc[mi][2 * g],     ah[mi], bh);
                    mma16816(acc[mi][2 * g],     ah[mi], bl);
                    mma16816(acc[mi][2 * g],     al[mi], bh);
                    mma16816(acc[mi][2 * g + 1], ah[mi], bh + 2);
                    mma16816(acc[mi][2 * g + 1], ah[mi], bl + 2);
                    mma16816(acc[mi][2 * g + 1], al[mi], bh + 2);
                }
            }
        }
        __syncthreads();
    }

    // ---- epilogue: stage fp32 tile [64][260], add (wh+wl), split, store ----
    float* Cs = (float*)smem;
    const int g4 = lane >> 2, tig = lane & 3;
#pragma unroll
    for (int mi = 0; mi < 2; mi++)
#pragma unroll
        for (int nj = 0; nj < 8; nj++) {
            int row = wm * 32 + mi * 16 + g4;
            int col = wn * 64 + nj * 8 + tig * 2;
            *(float2*)(Cs + row * LDCE + col)       = make_float2(acc[mi][nj][0], acc[mi][nj][1]);
            *(float2*)(Cs + (row + 8) * LDCE + col) = make_float2(acc[mi][nj][2], acc[mi][nj][3]);
        }
    __syncthreads();

    const int r = tid >> 2;
    const int ch = (tid & 3) * 64;
    const int gr = bm + r;
    const float* crow = Cs + r * LDCE + ch;
#pragma unroll
    for (int g = 0; g < 8; g++) {
        float v[8];
#pragma unroll
        for (int q = 0; q < 8; q++) v[q] = crow[g * 8 + q];
        size_t gcol = (size_t)gr * SDIM + ch + g * 8;
        uint4 hres = *(const uint4*)(Wh + gcol);
        uint4 lres = *(const uint4*)(Wl + gcol);
        const __nv_bfloat16* hp = (const __nv_bfloat16*)&hres;
        const __nv_bfloat16* lp = (const __nv_bfloat16*)&lres;
#pragma unroll
        for (int q = 0; q < 8; q++)
            v[q] += __bfloat162float(hp[q]) + __bfloat162float(lp[q]);
        __nv_bfloat16 hv[8], lv[8];
#pragma unroll
        for (int q = 0; q < 8; q++) split_bf(v[q], hv[q], lv[q]);
        *(uint4*)(outh + gcol) = *(const uint4*)hv;
        *(uint4*)(outl + gcol) = *(const uint4*)lv;
    }
}

// ---------------------------------------------------------------------------
// Fused scan stage d=2+4, BM=64, single-buffered smem, occupancy 2.
// ---------------------------------------------------------------------------
#define S3_AH    0
#define S3_B2    9792
#define S3_B4    46656
#define S3_SMEM  83520

__global__ __launch_bounds__(256, 2) void scan3(
    const __nv_bfloat16* __restrict__ Wh, const __nv_bfloat16* __restrict__ Wl,
    const __nv_bfloat16* __restrict__ P2h, const __nv_bfloat16* __restrict__ P4h,
    __nv_bfloat16* __restrict__ outh, __nv_bfloat16* __restrict__ outl)
{
    extern __shared__ char smem[];
    const int tid = threadIdx.x;
    const int bm = blockIdx.y * 64;
    const uint32_t sb = smem_u32(smem);
    const bool seqstart = ((bm & (LSEQ - 1)) == 0);

    const int w    = tid >> 5;
    const int lane = tid & 31;
    const int wm = w & 1;
    const int wn = w >> 1;
    const int lt = lane >> 3, lr = lane & 7;
    const uint32_t aLane = (uint32_t)(((lt & 1) * 8 + lr) * LROW + (lt >> 1) * 16);
    const uint32_t bLane = (uint32_t)(((lt >> 1) * 8 + lr) * LROW + (lt & 1) * 16);

    float acc[2][8][4];
#pragma unroll
    for (int i = 0; i < 2; i++)
#pragma unroll
        for (int j = 0; j < 8; j++)
#pragma unroll
            for (int q = 0; q < 4; q++) acc[i][j][q] = 0.f;

    for (int c = 0; c < 4; c++) {
        const int k0 = c * BKQ;
#pragma unroll
        for (int i = 0; i < 3; i++) {
            int e = tid + i * 256;
            if (e < 544) {
                int row = e >> 3, kc = e & 7;
                bool zero = seqstart && (row < 4);
                int g = zero ? bm : (bm - 4 + row);
                cp16z(sb + S3_AH + row * LROW + kc * 16,
                      Wh + (size_t)g * SDIM + k0 + kc * 8, zero ? 0 : 16);
            }
        }
#pragma unroll
        for (int i = 0; i < 8; i++) {
            int e = tid + i * 256;
            int row = e >> 3, kc = e & 7;
            size_t go = (size_t)row * SDIM + k0 + kc * 8;
            uint32_t so = sb + row * LROW + kc * 16;
            cp16(so + S3_B2, P2h + go);
            cp16(so + S3_B4, P4h + go);
        }
        CP_COMMIT();
        CP_WAIT0();
        __syncthreads();

        const uint32_t a2Base = sb + S3_AH + (2 + wm * 32) * LROW + aLane;
        const uint32_t a4Base = sb + S3_AH + (0 + wm * 32) * LROW + aLane;
        const uint32_t b2Base = sb + S3_B2 + (wn * 64) * LROW + bLane;
        const uint32_t b4Base = sb + S3_B4 + (wn * 64) * LROW + bLane;
#pragma unroll
        for (int kk = 0; kk < 4; kk++) {
            uint32_t a2[2][4], a4[2][4];
#pragma unroll
            for (int mi = 0; mi < 2; mi++) {
                ldm_x4(a2[mi], a2Base + mi * (16 * LROW) + kk * 32);
                ldm_x4(a4[mi], a4Base + mi * (16 * LROW) + kk * 32);
            }
#pragma unroll
            for (int g = 0; g < 4; g++) {
                uint32_t b2[4], b4[4];
                ldm_x4(b2, b2Base + g * (16 * LROW) + kk * 32);
                ldm_x4(b4, b4Base + g * (16 * LROW) + kk * 32);
#pragma unroll
                for (int mi = 0; mi < 2; mi++) {
                    mma16816(acc[mi][2 * g],     a2[mi], b2);
                    mma16816(acc[mi][2 * g + 1], a2[mi], b2 + 2);
                    mma16816(acc[mi][2 * g],     a4[mi], b4);
                    mma16816(acc[mi][2 * g + 1], a4[mi], b4 + 2);
                }
            }
        }
        __syncthreads();
    }

    float* Cs = (float*)smem;
    const int g4 = lane >> 2, tig = lane & 3;
#pragma unroll
    for (int mi = 0; mi < 2; mi++)
#pragma unroll
        for (int nj = 0; nj < 8; nj++) {
            int row = wm * 32 + mi * 16 + g4;
            int col = wn * 64 + nj * 8 + tig * 2;
            *(float2*)(Cs + row * LDCE + col)       = make_float2(acc[mi][nj][0], acc[mi][nj][1]);
            *(float2*)(Cs + (row + 8) * LDCE + col) = make_float2(acc[mi][nj][2], acc[mi][nj][3]);
        }
    __syncthreads();

    const int r = tid >> 2;
    const int ch = (tid & 3) * 64;
    const int gr = bm + r;
    const float* crow = Cs + r * LDCE + ch;
#pragma unroll
    for (int g = 0; g < 8; g++) {
        float v[8];
#pragma unroll
        for (int q = 0; q < 8; q++) v[q] = crow[g * 8 + q];
        size_t gcol = (size_t)gr * SDIM + ch + g * 8;
        uint4 hres = *(const uint4*)(Wh + gcol);
        uint4 lres = *(const uint4*)(Wl + gcol);
        const __nv_bfloat16* hp = (const __nv_bfloat16*)&hres;
        const __nv_bfloat16* lp = (const __nv_bfloat16*)&lres;
#pragma unroll
        for (int q = 0; q < 8; q++)
            v[q] += __bfloat162float(hp[q]) + __bfloat162float(lp[q]);
        __nv_bfloat16 hv[8], lv[8];
#pragma unroll
        for (int q = 0; q < 8; q++) split_bf(v[q], hv[q], lv[q]);
        *(uint4*)(outh + gcol) = *(const uint4*)hv;
        *(uint4*)(outl + gcol) = *(const uint4*)lv;
    }
}

// ---------------------------------------------------------------------------
// Fused GEMM2 + GELU + LayerNorm, BM=64, single-buffered smem, occupancy 2.
// ---------------------------------------------------------------------------
#define G2_AH    0
#define G2_AL    9216
#define G2_BH    18432
#define G2_BL    55296
#define G2_SMEM  92160

__global__ void __cluster_dims__(4, 1, 1) __launch_bounds__(256, 2)
gemm2_ln(const __nv_bfloat16* __restrict__ Ah, const __nv_bfloat16* __restrict__ Al,
         const __nv_bfloat16* __restrict__ Bh, const __nv_bfloat16* __restrict__ Bl,
         const float* __restrict__ gamma, const float* __restrict__ beta,
         float* __restrict__ out)
{
    extern __shared__ char smem[];
    __shared__ float2 part[64];
    const int tid = threadIdx.x;
    const int bm = blockIdx.y * 64;
    const int nb = blockIdx.x * 256;
    const int K = SDIM;
    const uint32_t sb = smem_u32(smem);

    const int w    = tid >> 5;
    const int lane = tid & 31;
    const int wm = w & 1;
    const int wn = w >> 1;

    const int lt = lane >> 3, lr = lane & 7;
    const uint32_t aLane = (uint32_t)(((lt & 1) * 8 + lr) * LROW + (lt >> 1) * 16);
    const uint32_t bLane = (uint32_t)(((lt >> 1) * 8 + lr) * LROW + (lt & 1) * 16);

    float acc[2][8][4];
#pragma unroll
    for (int i = 0; i < 2; i++)
#pragma unroll
        for (int j = 0; j < 8; j++)
#pragma unroll
            for (int q = 0; q < 4; q++) acc[i][j][q] = 0.f;

    for (int c = 0; c < 4; c++) {
        const int k0 = c * BKQ;
#pragma unroll
        for (int i = 0; i < 2; i++) {
            int e = tid + i * 256;
            int row = e >> 3, kc = e & 7;
            size_t go = (size_t)(bm + row) * K + k0 + kc * 8;
            uint32_t so = sb + row * LROW + kc * 16;
            cp16(so + G2_AH, Ah + go);
            cp16(so + G2_AL, Al + go);
        }
#pragma unroll
        for (int i = 0; i < 8; i++) {
            int e = tid + i * 256;
            int row = e >> 3, kc = e & 7;
            size_t go = (size_t)(nb + row) * K + k0 + kc * 8;
            uint32_t so = sb + row * LROW + kc * 16;
            cp16(so + G2_BH, Bh + go);
            cp16(so + G2_BL, Bl + go);
        }
        CP_COMMIT();
        CP_WAIT0();
        __syncthreads();

        const uint32_t aBase = sb + G2_AH + (wm * 32) * LROW + aLane;
        const uint32_t bBase = sb + G2_BH + (wn * 64) * LROW + bLane;
#pragma unroll
        for (int kk = 0; kk < 4; kk++) {
            uint32_t ah[2][4], al[2][4];
#pragma unroll
            for (int mi = 0; mi < 2; mi++) {
                uint32_t a0 = aBase + mi * (16 * LROW) + kk * 32;
                ldm_x4(ah[mi], a0);
                ldm_x4(al[mi], a0 + (G2_AL - G2_AH));
            }
#pragma unroll
            for (int g = 0; g < 4; g++) {
                uint32_t bh[4], bl[4];
                uint32_t b0 = bBase + g * (16 * LROW) + kk * 32;
                ldm_x4(bh, b0);
                ldm_x4(bl, b0 + (G2_BL - G2_BH));
#pragma unroll
                for (int mi = 0; mi < 2; mi++) {
                    mma16816(acc[mi][2 * g],     ah[mi], bh);
                    mma16816(acc[mi][2 * g],     ah[mi], bl);
                    mma16816(acc[mi][2 * g],     al[mi], bh);
                    mma16816(acc[mi][2 * g + 1], ah[mi], bh + 2);
                    mma16816(acc[mi][2 * g + 1], ah[mi], bl + 2);
                    mma16816(acc[mi][2 * g + 1], al[mi], bh + 2);
                }
            }
        }
        __syncthreads();
    }

    float* Cs = (float*)smem;
    const int g4 = lane >> 2, tig = lane & 3;
#pragma unroll
    for (int mi = 0; mi < 2; mi++)
#pragma unroll
        for (int nj = 0; nj < 8; nj++) {
            int row = wm * 32 + mi * 16 + g4;
            int col = wn * 64 + nj * 8 + tig * 2;
            *(float2*)(Cs + row * LDCE + col)       = make_float2(acc[mi][nj][0], acc[mi][nj][1]);
            *(float2*)(Cs + (row + 8) * LDCE + col) = make_float2(acc[mi][nj][2], acc[mi][nj][3]);
        }
    __syncthreads();

    const int r = tid >> 2;
    const int ch = (tid & 3) * 64;
    float* crow = Cs + r * LDCE + ch;
    float s = 0.f, sq = 0.f;
#pragma unroll
    for (int g = 0; g < 16; g++) {
        float4 v = *(const float4*)(crow + g * 4);
        v.x = gelu_exact(v.x); v.y = gelu_exact(v.y);
        v.z = gelu_exact(v.z); v.w = gelu_exact(v.w);
        *(float4*)(crow + g * 4) = v;
        s  += v.x + v.y + v.z + v.w;
        sq += v.x * v.x + v.y * v.y + v.z * v.z + v.w * v.w;
    }
    s  += __shfl_xor_sync(0xffffffffu, s, 1);
    sq += __shfl_xor_sync(0xffffffffu, sq, 1);
    s  += __shfl_xor_sync(0xffffffffu, s, 2);
    sq += __shfl_xor_sync(0xffffffffu, sq, 2);
    if ((tid & 3) == 0) part[r] = make_float2(s, sq);

    cg::cluster_group cluster = cg::this_cluster();
    cluster.sync();
    float S = 0.f, SQ = 0.f;
#pragma unroll
    for (unsigned rk = 0; rk < 4; rk++) {
        const float2* pp = cluster.map_shared_rank(part, rk);
        float2 p = pp[r];
        S += p.x; SQ += p.y;
    }
    const float mean = S * (1.f / DMOD);
    const float var  = SQ * (1.f / DMOD) - mean * mean;
    const float rstd = rsqrtf(var + 1e-5f);

    float* po = out + (size_t)(bm + r) * DMOD + nb + ch;
    const float* gm = gamma + nb + ch;
    const float* bt = beta + nb + ch;
#pragma unroll
    for (int g = 0; g < 16; g++) {
        float4 v  = *(const float4*)(crow + g * 4);
        float4 gg = *(const float4*)(gm + g * 4);
        float4 bb = *(const float4*)(bt + g * 4);
        float4 o;
        o.x = (v.x - mean) * rstd * gg.x + bb.x;
        o.y = (v.y - mean) * rstd * gg.y + bb.y;
        o.z = (v.z - mean) * rstd * gg.z + bb.z;
        o.w = (v.w - mean) * rstd * gg.w + bb.w;
        *(float4*)(po + g * 4) = o;
    }
    cluster.sync();
}

// ---------------------------------------------------------------------------
// kernel_launch — fork prep onto a side stream to overlap with GEMM1.
// ---------------------------------------------------------------------------
extern "C" void kernel_launch(void* const* d_in, const int* in_sizes, int n_in,
                              void* d_out, int out_size)
{
    const float* x     = (const float*)d_in[0];
    const float* A     = (const float*)d_in[1];
    const float* Bmat  = (const float*)d_in[2];
    const float* C     = (const float*)d_in[3];
    const float* gamma = (const float*)d_in[4];
    const float* beta  = (const float*)d_in[5];
    float* out = (float*)d_out;

    __nv_bfloat16 *wh0, *wl0, *wh1, *wl1, *Bh, *Bl, *Ch, *Cl, *Ph, *Pl, *P2h;
    float *P;
    cudaGetSymbolAddress((void**)&wh0, g_wh);   wh1 = wh0 + (size_t)MROWS * SDIM;
    cudaGetSymbolAddress((void**)&wl0, g_wl);   wl1 = wl0 + (size_t)MROWS * SDIM;
    cudaGetSymbolAddress((void**)&Bh, g_Bh);
    cudaGetSymbolAddress((void**)&Bl, g_Bl);
    cudaGetSymbolAddress((void**)&Ch, g_Ch);
    cudaGetSymbolAddress((void**)&Cl, g_Cl);
    cudaGetSymbolAddress((void**)&P,  g_P);
    cudaGetSymbolAddress((void**)&Ph, g_Ph);
    cudaGetSymbolAddress((void**)&Pl, g_Pl);
    cudaGetSymbolAddress((void**)&P2h, g_P2h);

    cudaFuncSetAttribute((void*)gemm1,    cudaFuncAttributeMaxDynamicSharedMemorySize, SMEM_SZ);
    cudaFuncSetAttribute((void*)scan1,    cudaFuncAttributeMaxDynamicSharedMemorySize, S1_SMEM);
    cudaFuncSetAttribute((void*)scan3,    cudaFuncAttributeMaxDynamicSharedMemorySize, S3_SMEM);
    cudaFuncSetAttribute((void*)gemm2_ln, cudaFuncAttributeMaxDynamicSharedMemorySize, G2_SMEM);

    // ---- fork: side stream runs C/A-prep + matrix powers concurrently ----
    cudaEventRecord(g_ss.eFork, 0);
    cudaStreamWaitEvent(g_ss.s2, g_ss.eFork, 0);

    const int n2 = (DMOD * SDIM + SDIM * SDIM + 2 * SDIM * SDIM) / 4;
    prep2<<<(n2 + 255) / 256, 256, 0, g_ss.s2>>>(C, A, Ch, Cl, Ph, Pl, P);
    const dim3 skgrid(4, 4, 8);
    matsq_sk<<<skgrid, 256, 0, g_ss.s2>>>(A, P);                  // A^2
    matsq_sk<<<skgrid, 256, 0, g_ss.s2>>>(P, P + SDIM * SDIM);    // A^4
    conv_hi<<<2 * SDIM * SDIM / 4 / 256, 256, 0, g_ss.s2>>>(P, P2h, 2 * SDIM * SDIM / 4);
    cudaEventRecord(g_ss.eJoin, g_ss.s2);

    // ---- main stream: B split, GEMM1 ----
    bsplit<<<SDIM * DMOD / 4 / 256, 256>>>(Bmat, Bh, Bl);
    gemm1<<<dim3(1, MROWS / 128), NTHR, SMEM_SZ>>>(x, Bh, Bl, wh0, wl0, DMOD);

    // ---- join ----
    cudaStreamWaitEvent(0, g_ss.eJoin, 0);

    // ---- scan: d=1 (3-term, BM=64 occ 2), then fused d=2+4 ----
    scan1<<<dim3(1, MROWS / 64), 256, S1_SMEM>>>(wh0, wl0, Ph, Pl, wh1, wl1);
    scan3<<<dim3(1, MROWS / 64), 256, S3_SMEM>>>(
        wh1, wl1, P2h, P2h + SDIM * SDIM, wh0, wl0);

    // ---- GEMM2 + GELU + LayerNorm fused (BM=64, occ 2, cluster over N) ----
    gemm2_ln<<<dim3(DMOD / 256, MROWS / 64), 256, G2_SMEM>>>(
        wh0, wl0, Ch, Cl, gamma, beta, out);
}

// round 17
// speedup vs baseline: 1.0183x; 1.0183x over previous
#include <cuda_runtime.h>
#include <cuda_bf16.h>
#include <cooperative_groups.h>
#include <math.h>
#include <stdint.h>

namespace cg = cooperative_groups;

#define BSZ   8
#define LSEQ  2048
#define DMOD  1024
#define SDIM  256
#define MROWS (BSZ*LSEQ)   // 16384

// ---------------------------------------------------------------------------
// Static device scratch
// ---------------------------------------------------------------------------
__device__ __align__(128) __nv_bfloat16 g_wh[2][(size_t)MROWS * SDIM];
__device__ __align__(128) __nv_bfloat16 g_wl[2][(size_t)MROWS * SDIM];
__device__ __align__(128) __nv_bfloat16 g_Bh[SDIM * DMOD];
__device__ __align__(128) __nv_bfloat16 g_Bl[SDIM * DMOD];
__device__ __align__(128) __nv_bfloat16 g_Ch[DMOD * SDIM];
__device__ __align__(128) __nv_bfloat16 g_Cl[DMOD * SDIM];
__device__ __align__(128) float         g_P[2][SDIM * SDIM];      // A^2, A^4 fp32
__device__ __align__(128) __nv_bfloat16 g_Ph[SDIM * SDIM];        // A hi (d=1)
__device__ __align__(128) __nv_bfloat16 g_Pl[SDIM * SDIM];        // A lo (unused now, kept)
__device__ __align__(128) __nv_bfloat16 g_P2h[2][SDIM * SDIM];    // A^2, A^4 hi

// ---------------------------------------------------------------------------
// Side stream + fork/join events (created once at static init).
// ---------------------------------------------------------------------------
struct SideStream {
    cudaStream_t s2;
    cudaEvent_t  eFork, eJoin;
    SideStream() {
        cudaStreamCreateWithFlags(&s2, cudaStreamNonBlocking);
        cudaEventCreateWithFlags(&eFork, cudaEventDisableTiming);
        cudaEventCreateWithFlags(&eJoin, cudaEventDisableTiming);
    }
};
static SideStream g_ss;

// ---------------------------------------------------------------------------
// PTX helpers (base sm_80+ ISA only)
// ---------------------------------------------------------------------------
__device__ __forceinline__ uint32_t smem_u32(const void* p) {
    uint32_t a;
    asm("{ .reg .u64 t; cvta.to.shared.u64 t, %1; cvt.u32.u64 %0, t; }" : "=r"(a) : "l"(p));
    return a;
}
__device__ __forceinline__ void cp16(uint32_t s, const void* g) {
    asm volatile("cp.async.cg.shared.global [%0], [%1], 16;" :: "r"(s), "l"(g));
}
__device__ __forceinline__ void cp16z(uint32_t s, const void* g, int sz) {
    asm volatile("cp.async.cg.shared.global [%0], [%1], 16, %2;" :: "r"(s), "l"(g), "r"(sz));
}
#define CP_COMMIT()   asm volatile("cp.async.commit_group;" ::: "memory")
#define CP_WAIT0()    asm volatile("cp.async.wait_group 0;" ::: "memory")

__device__ __forceinline__ void ldm_x4(uint32_t* r, uint32_t saddr) {
    asm volatile("ldmatrix.sync.aligned.m8n8.x4.shared.b16 {%0,%1,%2,%3}, [%4];"
        : "=r"(r[0]), "=r"(r[1]), "=r"(r[2]), "=r"(r[3]) : "r"(saddr));
}
__device__ __forceinline__ void mma16816(float* c, const uint32_t* a, const uint32_t* b) {
    asm volatile("mma.sync.aligned.m16n8k16.row.col.f32.bf16.bf16.f32 "
        "{%0,%1,%2,%3}, {%4,%5,%6,%7}, {%8,%9}, {%0,%1,%2,%3};"
        : "+f"(c[0]), "+f"(c[1]), "+f"(c[2]), "+f"(c[3])
        : "r"(a[0]), "r"(a[1]), "r"(a[2]), "r"(a[3]), "r"(b[0]), "r"(b[1]));
}

__device__ __forceinline__ float gelu_exact(float x) {
    return 0.5f * x * (1.0f + erff(x * 0.7071067811865476f));
}
__device__ __forceinline__ void split_bf(float v, __nv_bfloat16& h, __nv_bfloat16& l) {
    h = __float2bfloat16(v);
    l = __float2bfloat16(v - __bfloat162float(h));
}
__device__ __forceinline__ void pack_split4(float4 v, uint2& hv, uint2& lv) {
    __nv_bfloat16 h0, h1, h2, h3, l0, l1, l2, l3;
    split_bf(v.x, h0, l0); split_bf(v.y, h1, l1);
    split_bf(v.z, h2, l2); split_bf(v.w, h3, l3);
    hv.x = (uint32_t)__bfloat16_as_ushort(h0) | ((uint32_t)__bfloat16_as_ushort(h1) << 16);
    hv.y = (uint32_t)__bfloat16_as_ushort(h2) | ((uint32_t)__bfloat16_as_ushort(h3) << 16);
    lv.x = (uint32_t)__bfloat16_as_ushort(l0) | ((uint32_t)__bfloat16_as_ushort(l1) << 16);
    lv.y = (uint32_t)__bfloat16_as_ushort(l2) | ((uint32_t)__bfloat16_as_ushort(l3) << 16);
}
__device__ __forceinline__ uint2 pack_hi4(float4 v) {
    uint2 hv;
    hv.x = (uint32_t)__bfloat16_as_ushort(__float2bfloat16(v.x))
         | ((uint32_t)__bfloat16_as_ushort(__float2bfloat16(v.y)) << 16);
    hv.y = (uint32_t)__bfloat16_as_ushort(__float2bfloat16(v.z))
         | ((uint32_t)__bfloat16_as_ushort(__float2bfloat16(v.w)) << 16);
    return hv;
}

// ---------------------------------------------------------------------------
// bsplit / prep2 / conv_hi / matsq_sk
// ---------------------------------------------------------------------------
__global__ void bsplit(const float* __restrict__ Bm,
                       __nv_bfloat16* __restrict__ Bh, __nv_bfloat16* __restrict__ Bl) {
    int i = blockIdx.x * blockDim.x + threadIdx.x;
    if (i >= SDIM * DMOD / 4) return;
    float4 v = ((const float4*)Bm)[i];
    uint2 hv, lv;
    pack_split4(v, hv, lv);
    ((uint2*)Bh)[i] = hv;
    ((uint2*)Bl)[i] = lv;
}

__global__ void prep2(const float* __restrict__ C, const float* __restrict__ A,
                      __nv_bfloat16* __restrict__ Ch, __nv_bfloat16* __restrict__ Cl,
                      __nv_bfloat16* __restrict__ Ph, __nv_bfloat16* __restrict__ Pl,
                      float* __restrict__ P) {
    const int nC = DMOD * SDIM / 4, nA = SDIM * SDIM / 4;
    const int nZ = 2 * SDIM * SDIM / 4;
    int i = blockIdx.x * blockDim.x + threadIdx.x;
    const float* src; __nv_bfloat16 *h, *l; int j;
    if (i < nC)           { src = C; h = Ch; l = Cl; j = i; }
    else if (i < nC + nA) { src = A; h = Ph; l = Pl; j = i - nC; }
    else if (i < nC + nA + nZ) {
        ((float4*)P)[i - nC - nA] = make_float4(0.f, 0.f, 0.f, 0.f);
        return;
    } else return;
    float4 v = ((const float4*)src)[j];
    uint2 hv, lv;
    pack_split4(v, hv, lv);
    ((uint2*)h)[j] = hv;
    ((uint2*)l)[j] = lv;
}

__global__ void conv_hi(const float* __restrict__ in,
                        __nv_bfloat16* __restrict__ h, int n4) {
    int i = blockIdx.x * blockDim.x + threadIdx.x;
    if (i >= n4) return;
    ((uint2*)h)[i] = pack_hi4(((const float4*)in)[i]);
}

__global__ __launch_bounds__(256) void matsq_sk(const float* __restrict__ In,
                                                float* __restrict__ Out) {
    __shared__ float sA[64][33];
    __shared__ float sB[32][65];
    const int tid = threadIdx.x;
    const int i0 = blockIdx.y * 64, j0 = blockIdx.x * 64, k0 = blockIdx.z * 32;
#pragma unroll
    for (int i = 0; i < 8; i++) {
        int e = tid + i * 256;
        int ar = e >> 5, ak = e & 31;
        sA[ar][ak] = In[(i0 + ar) * SDIM + k0 + ak];
        int br = e >> 6, bc = e & 63;
        sB[br][bc] = In[(k0 + br) * SDIM + j0 + bc];
    }
    __syncthreads();
    const int ty = tid >> 4, tx = tid & 15;
    float acc[4][4] = {};
#pragma unroll
    for (int k = 0; k < 32; k++) {
        float a[4], b[4];
#pragma unroll
        for (int q = 0; q < 4; q++) a[q] = sA[ty * 4 + q][k];
#pragma unroll
        for (int q = 0; q < 4; q++) b[q] = sB[k][tx * 4 + q];
#pragma unroll
        for (int q = 0; q < 4; q++)
#pragma unroll
            for (int r = 0; r < 4; r++) acc[q][r] = fmaf(a[q], b[r], acc[q][r]);
    }
#pragma unroll
    for (int q = 0; q < 4; q++)
#pragma unroll
        for (int r = 0; r < 4; r++)
            atomicAdd(&Out[(i0 + ty * 4 + q) * SDIM + j0 + tx * 4 + r], acc[q][r]);
}

// ---------------------------------------------------------------------------
// GEMM1 (at floor): C[128 x 256] = x[M,K] @ B[N,K]^T, 512 threads, 3-term.
// ---------------------------------------------------------------------------
#define BKQ      64
#define LROW     144
#define A_H_OFF  0
#define A_L_OFF  18432
#define B_H_OFF  36864
#define B_L_OFF  73728
#define STAGE_B  110592
#define SMEM_SZ  (2 * STAGE_B)
#define LDCE     260
#define NTHR     512

__global__ __launch_bounds__(NTHR, 1) void gemm1(
    const float* __restrict__ Xf,
    const __nv_bfloat16* __restrict__ Bh, const __nv_bfloat16* __restrict__ Bl,
    __nv_bfloat16* __restrict__ outh, __nv_bfloat16* __restrict__ outl,
    int K)
{
    extern __shared__ char smem[];
    const int tid = threadIdx.x;
    const int bm = blockIdx.y * 128;
    const int NC = K / BKQ;
    const uint32_t sb = smem_u32(smem);

    const int w    = tid >> 5;
    const int lane = tid & 31;
    const int wm = w & 3;
    const int wn = w >> 2;

    const int lt = lane >> 3, lr = lane & 7;
    const uint32_t aLane = (uint32_t)(((lt & 1) * 8 + lr) * LROW + (lt >> 1) * 16);
    const uint32_t bLane = (uint32_t)(((lt >> 1) * 8 + lr) * LROW + (lt & 1) * 16);

    float acc[2][8][4];
#pragma unroll
    for (int i = 0; i < 2; i++)
#pragma unroll
        for (int j = 0; j < 8; j++)
#pragma unroll
            for (int q = 0; q < 4; q++) acc[i][j][q] = 0.f;

    float4 xr[4];

    auto ldregs = [&](int c) {
        const int k0 = c * BKQ;
#pragma unroll
        for (int i = 0; i < 4; i++) {
            int e = tid + i * NTHR;
            int row = e >> 4, cgp = e & 15;
            xr[i] = *(const float4*)(Xf + (size_t)(bm + row) * K + k0 + cgp * 4);
        }
    };
    auto st_A = [&](int buf) {
        char* base = smem + buf * STAGE_B;
#pragma unroll
        for (int i = 0; i < 4; i++) {
            int e = tid + i * NTHR;
            int row = e >> 4, cgp = e & 15;
            uint2 hv, lv;
            pack_split4(xr[i], hv, lv);
            uint32_t so = row * LROW + cgp * 8;
            *(uint2*)(base + A_H_OFF + so) = hv;
            *(uint2*)(base + A_L_OFF + so) = lv;
        }
    };
    auto issueB = [&](int c, int buf) {
        const uint32_t base = sb + buf * STAGE_B;
        const int k0 = c * BKQ;
#pragma unroll
        for (int i = 0; i < 4; i++) {
            int e = tid + i * NTHR;
            int row = e >> 3, kc = e & 7;
            size_t go = (size_t)row * K + k0 + kc * 8;
            uint32_t so = base + row * LROW + kc * 16;
            cp16(so + B_H_OFF, Bh + go);
            cp16(so + B_L_OFF, Bl + go);
        }
    };
    auto compute = [&](int b) {
        const uint32_t aBase = sb + b * STAGE_B + A_H_OFF + (wm * 32) * LROW + aLane;
        const uint32_t bBase = sb + b * STAGE_B + B_H_OFF + (wn * 64) * LROW + bLane;
#pragma unroll
        for (int kk = 0; kk < 4; kk++) {
            uint32_t ah[2][4], al[2][4];
#pragma unroll
            for (int mi = 0; mi < 2; mi++) {
                uint32_t a0 = aBase + mi * (16 * LROW) + kk * 32;
                ldm_x4(ah[mi], a0);
                ldm_x4(al[mi], a0 + (A_L_OFF - A_H_OFF));
            }
#pragma unroll
            for (int g = 0; g < 4; g++) {
                uint32_t bh[4], bl[4];
                uint32_t b0 = bBase + g * (16 * LROW) + kk * 32;
                ldm_x4(bh, b0);
                ldm_x4(bl, b0 + (B_L_OFF - B_H_OFF));
#pragma unroll
                for (int mi = 0; mi < 2; mi++) {
                    mma16816(acc[mi][2 * g],     ah[mi], bh);
                    mma16816(acc[mi][2 * g],     ah[mi], bl);
                    mma16816(acc[mi][2 * g],     al[mi], bh);
                    mma16816(acc[mi][2 * g + 1], ah[mi], bh + 2);
                    mma16816(acc[mi][2 * g + 1], ah[mi], bl + 2);
                    mma16816(acc[mi][2 * g + 1], al[mi], bh + 2);
                }
            }
        }
    };

    ldregs(0); st_A(0);
    issueB(0, 0);
    CP_COMMIT();

    for (int c = 0; c < NC; c++) {
        const int b = c & 1;
        const bool more = (c + 1 < NC);
        if (more) ldregs(c + 1);
        CP_WAIT0();
        __syncthreads();
        if (more) { issueB(c + 1, b ^ 1); CP_COMMIT(); }
        compute(b);
        if (more) st_A(b ^ 1);
    }
    __syncthreads();

    float* Cs = (float*)smem;
    const int g4 = lane >> 2, tig = lane & 3;
#pragma unroll
    for (int mi = 0; mi < 2; mi++)
#pragma unroll
        for (int nj = 0; nj < 8; nj++) {
            int row = wm * 32 + mi * 16 + g4;
            int col = wn * 64 + nj * 8 + tig * 2;
            *(float2*)(Cs + row * LDCE + col)       = make_float2(acc[mi][nj][0], acc[mi][nj][1]);
            *(float2*)(Cs + (row + 8) * LDCE + col) = make_float2(acc[mi][nj][2], acc[mi][nj][3]);
        }
    __syncthreads();

    const int r = tid >> 2;
    const int ch = (tid & 3) * 64;
    const int gr = bm + r;
    const float* crow = Cs + r * LDCE + ch;

#pragma unroll
    for (int g = 0; g < 8; g++) {
        float v[8];
#pragma unroll
        for (int q = 0; q < 8; q++) v[q] = crow[g * 8 + q];
        size_t gcol = (size_t)gr * SDIM + ch + g * 8;
        __nv_bfloat16 hv[8], lv[8];
#pragma unroll
        for (int q = 0; q < 8; q++) split_bf(v[q], hv[q], lv[q]);
        *(uint4*)(outh + gcol) = *(const uint4*)hv;
        *(uint4*)(outl + gcol) = *(const uint4*)lv;
    }
}

// ---------------------------------------------------------------------------
// scan1: d=1 stage, BM=64, 2-TERM (ah·bh + al·bh; w_hi·A_lo dropped — R9-
// anchored error estimate ~2.7e-4). B = A hi only -> smem 66.6 KB (epilogue-
// bound), occupancy 3.
//   out = (wh+wl) + [shift(wh,1) + shift(wl,1)] @ Ah^T
// smem: A h/l (2*9216) + Bh (36864) = 55296; epilogue fp32 [64][260] = 66560.
// ---------------------------------------------------------------------------
#define S1_AH    0
#define S1_AL    9216
#define S1_BH    18432
#define S1_SMEM  66560

__global__ __launch_bounds__(256, 2) void scan1(
    const __nv_bfloat16* __restrict__ Wh, const __nv_bfloat16* __restrict__ Wl,
    const __nv_bfloat16* __restrict__ Ph,
    __nv_bfloat16* __restrict__ outh, __nv_bfloat16* __restrict__ outl)
{
    extern __shared__ char smem[];
    const int tid = threadIdx.x;
    const int bm = blockIdx.y * 64;
    const uint32_t sb = smem_u32(smem);

    const int w    = tid >> 5;
    const int lane = tid & 31;
    const int wm = w & 1;
    const int wn = w >> 1;
    const int lt = lane >> 3, lr = lane & 7;
    const uint32_t aLane = (uint32_t)(((lt & 1) * 8 + lr) * LROW + (lt >> 1) * 16);
    const uint32_t bLane = (uint32_t)(((lt >> 1) * 8 + lr) * LROW + (lt & 1) * 16);

    float acc[2][8][4];
#pragma unroll
    for (int i = 0; i < 2; i++)
#pragma unroll
        for (int j = 0; j < 8; j++)
#pragma unroll
            for (int q = 0; q < 4; q++) acc[i][j][q] = 0.f;

    for (int c = 0; c < 4; c++) {
        const int k0 = c * BKQ;
        // A: 64 rows, shifted by 1 (zero-fill at sequence start), h and l
#pragma unroll
        for (int i = 0; i < 2; i++) {
            int e = tid + i * 256;
            int row = e >> 3, kc = e & 7;
            int gr = bm + row;
            int t = gr & (LSEQ - 1);
            int sz = (t >= 1) ? 16 : 0;
            int srow = gr - (t >= 1 ? 1 : 0);
            size_t go = (size_t)srow * SDIM + k0 + kc * 8;
            uint32_t so = sb + row * LROW + kc * 16;
            cp16z(so + S1_AH, Wh + go, sz);
            cp16z(so + S1_AL, Wl + go, sz);
        }
        // B: 256 rows of A, hi only
#pragma unroll
        for (int i = 0; i < 8; i++) {
            int e = tid + i * 256;
            int row = e >> 3, kc = e & 7;
            cp16(sb + S1_BH + row * LROW + kc * 16,
                 Ph + (size_t)row * SDIM + k0 + kc * 8);
        }
        CP_COMMIT();
        CP_WAIT0();
        __syncthreads();

        const uint32_t aBase = sb + S1_AH + (wm * 32) * LROW + aLane;
        const uint32_t bBase = sb + S1_BH + (wn * 64) * LROW + bLane;
#pragma unroll
        for (int kk = 0; kk < 4; kk++) {
            uint32_t ah[2][4], al[2][4];
#pragma unroll
            for (int mi = 0; mi < 2; mi++) {
                uint32_t a0 = aBase + mi * (16 * LROW) + kk * 32;
                ldm_x4(ah[mi], a0);
                ldm_x4(al[mi], a0 + (S1_AL - S1_AH));
            }
#pragma unroll
            for (int g = 0; g < 4; g++) {
                uint32_t bh[4];
                ldm_x4(bh, bBase + g * (16 * LROW) + kk * 32);
#pragma unroll
                for (int mi = 0; mi < 2; mi++) {
                    mma16816(acc[mi][2 * g],     ah[mi], bh);
                    mma16816(acc[mi][2 * g],     al[mi], bh);
                    mma16816(acc[mi][2 * g + 1], ah[mi], bh + 2);
                    mma16816(acc[mi][2 * g + 1], al[mi], bh + 2);
                }
            }
        }
        __syncthreads();
    }

    // ---- epilogue: stage fp32 tile [64][260], add (wh+wl), split, store ----
    float* Cs = (float*)smem;
    const int g4 = lane >> 2, tig = lane & 3;
#pragma unroll
    for (int mi = 0; mi < 2; mi++)
#pragma unroll
        for (int nj = 0; nj < 8; nj++) {
            int row = wm * 32 + mi * 16 + g4;
            int col = wn * 64 + nj * 8 + tig * 2;
            *(float2*)(Cs + row * LDCE + col)       = make_float2(acc[mi][nj][0], acc[mi][nj][1]);
            *(float2*)(Cs + (row + 8) * LDCE + col) = make_float2(acc[mi][nj][2], acc[mi][nj][3]);
        }
    __syncthreads();

    const int r = tid >> 2;
    const int ch = (tid & 3) * 64;
    const int gr = bm + r;
    const float* crow = Cs + r * LDCE + ch;
#pragma unroll
    for (int g = 0; g < 8; g++) {
        float v[8];
#pragma unroll
        for (int q = 0; q < 8; q++) v[q] = crow[g * 8 + q];
        size_t gcol = (size_t)gr * SDIM + ch + g * 8;
        uint4 hres = *(const uint4*)(Wh + gcol);
        uint4 lres = *(const uint4*)(Wl + gcol);
        const __nv_bfloat16* hp = (const __nv_bfloat16*)&hres;
        const __nv_bfloat16* lp = (const __nv_bfloat16*)&lres;
#pragma unroll
        for (int q = 0; q < 8; q++)
            v[q] += __bfloat162float(hp[q]) + __bfloat162float(lp[q]);
        __nv_bfloat16 hv[8], lv[8];
#pragma unroll
        for (int q = 0; q < 8; q++) split_bf(v[q], hv[q], lv[q]);
        *(uint4*)(outh + gcol) = *(const uint4*)hv;
        *(uint4*)(outl + gcol) = *(const uint4*)lv;
    }
}

// ---------------------------------------------------------------------------
// Fused scan stage d=2+4, BM=64, single-buffered smem, occupancy 2.
// ---------------------------------------------------------------------------
#define S3_AH    0
#define S3_B2    9792
#define S3_B4    46656
#define S3_SMEM  83520

__global__ __launch_bounds__(256, 2) void scan3(
    const __nv_bfloat16* __restrict__ Wh, const __nv_bfloat16* __restrict__ Wl,
    const __nv_bfloat16* __restrict__ P2h, const __nv_bfloat16* __restrict__ P4h,
    __nv_bfloat16* __restrict__ outh, __nv_bfloat16* __restrict__ outl)
{
    extern __shared__ char smem[];
    const int tid = threadIdx.x;
    const int bm = blockIdx.y * 64;
    const uint32_t sb = smem_u32(smem);
    const bool seqstart = ((bm & (LSEQ - 1)) == 0);

    const int w    = tid >> 5;
    const int lane = tid & 31;
    const int wm = w & 1;
    const int wn = w >> 1;
    const int lt = lane >> 3, lr = lane & 7;
    const uint32_t aLane = (uint32_t)(((lt & 1) * 8 + lr) * LROW + (lt >> 1) * 16);
    const uint32_t bLane = (uint32_t)(((lt >> 1) * 8 + lr) * LROW + (lt & 1) * 16);

    float acc[2][8][4];
#pragma unroll
    for (int i = 0; i < 2; i++)
#pragma unroll
        for (int j = 0; j < 8; j++)
#pragma unroll
            for (int q = 0; q < 4; q++) acc[i][j][q] = 0.f;

    for (int c = 0; c < 4; c++) {
        const int k0 = c * BKQ;
#pragma unroll
        for (int i = 0; i < 3; i++) {
            int e = tid + i * 256;
            if (e < 544) {
                int row = e >> 3, kc = e & 7;
                bool zero = seqstart && (row < 4);
                int g = zero ? bm : (bm - 4 + row);
                cp16z(sb + S3_AH + row * LROW + kc * 16,
                      Wh + (size_t)g * SDIM + k0 + kc * 8, zero ? 0 : 16);
            }
        }
#pragma unroll
        for (int i = 0; i < 8; i++) {
            int e = tid + i * 256;
            int row = e >> 3, kc = e & 7;
            size_t go = (size_t)row * SDIM + k0 + kc * 8;
            uint32_t so = sb + row * LROW + kc * 16;
            cp16(so + S3_B2, P2h + go);
            cp16(so + S3_B4, P4h + go);
        }
        CP_COMMIT();
        CP_WAIT0();
        __syncthreads();

        const uint32_t a2Base = sb + S3_AH + (2 + wm * 32) * LROW + aLane;
        const uint32_t a4Base = sb + S3_AH + (0 + wm * 32) * LROW + aLane;
        const uint32_t b2Base = sb + S3_B2 + (wn * 64) * LROW + bLane;
        const uint32_t b4Base = sb + S3_B4 + (wn * 64) * LROW + bLane;
#pragma unroll
        for (int kk = 0; kk < 4; kk++) {
            uint32_t a2[2][4], a4[2][4];
#pragma unroll
            for (int mi = 0; mi < 2; mi++) {
                ldm_x4(a2[mi], a2Base + mi * (16 * LROW) + kk * 32);
                ldm_x4(a4[mi], a4Base + mi * (16 * LROW) + kk * 32);
            }
#pragma unroll
            for (int g = 0; g < 4; g++) {
                uint32_t b2[4], b4[4];
                ldm_x4(b2, b2Base + g * (16 * LROW) + kk * 32);
                ldm_x4(b4, b4Base + g * (16 * LROW) + kk * 32);
#pragma unroll
                for (int mi = 0; mi < 2; mi++) {
                    mma16816(acc[mi][2 * g],     a2[mi], b2);
                    mma16816(acc[mi][2 * g + 1], a2[mi], b2 + 2);
                    mma16816(acc[mi][2 * g],     a4[mi], b4);
                    mma16816(acc[mi][2 * g + 1], a4[mi], b4 + 2);
                }
            }
        }
        __syncthreads();
    }

    float* Cs = (float*)smem;
    const int g4 = lane >> 2, tig = lane & 3;
#pragma unroll
    for (int mi = 0; mi < 2; mi++)
#pragma unroll
        for (int nj = 0; nj < 8; nj++) {
            int row = wm * 32 + mi * 16 + g4;
            int col = wn * 64 + nj * 8 + tig * 2;
            *(float2*)(Cs + row * LDCE + col)       = make_float2(acc[mi][nj][0], acc[mi][nj][1]);
            *(float2*)(Cs + (row + 8) * LDCE + col) = make_float2(acc[mi][nj][2], acc[mi][nj][3]);
        }
    __syncthreads();

    const int r = tid >> 2;
    const int ch = (tid & 3) * 64;
    const int gr = bm + r;
    const float* crow = Cs + r * LDCE + ch;
#pragma unroll
    for (int g = 0; g < 8; g++) {
        float v[8];
#pragma unroll
        for (int q = 0; q < 8; q++) v[q] = crow[g * 8 + q];
        size_t gcol = (size_t)gr * SDIM + ch + g * 8;
        uint4 hres = *(const uint4*)(Wh + gcol);
        uint4 lres = *(const uint4*)(Wl + gcol);
        const __nv_bfloat16* hp = (const __nv_bfloat16*)&hres;
        const __nv_bfloat16* lp = (const __nv_bfloat16*)&lres;
#pragma unroll
        for (int q = 0; q < 8; q++)
            v[q] += __bfloat162float(hp[q]) + __bfloat162float(lp[q]);
        __nv_bfloat16 hv[8], lv[8];
#pragma unroll
        for (int q = 0; q < 8; q++) split_bf(v[q], hv[q], lv[q]);
        *(uint4*)(outh + gcol) = *(const uint4*)hv;
        *(uint4*)(outl + gcol) = *(const uint4*)lv;
    }
}

// ---------------------------------------------------------------------------
// Fused GEMM2 + GELU + LayerNorm, BM=64, single-buffered smem, occupancy 2.
// ---------------------------------------------------------------------------
#define G2_AH    0
#define G2_AL    9216
#define G2_BH    18432
#define G2_BL    55296
#define G2_SMEM  92160

__global__ void __cluster_dims__(4, 1, 1) __launch_bounds__(256, 2)
gemm2_ln(const __nv_bfloat16* __restrict__ Ah, const __nv_bfloat16* __restrict__ Al,
         const __nv_bfloat16* __restrict__ Bh, const __nv_bfloat16* __restrict__ Bl,
         const float* __restrict__ gamma, const float* __restrict__ beta,
         float* __restrict__ out)
{
    extern __shared__ char smem[];
    __shared__ float2 part[64];
    const int tid = threadIdx.x;
    const int bm = blockIdx.y * 64;
    const int nb = blockIdx.x * 256;
    const int K = SDIM;
    const uint32_t sb = smem_u32(smem);

    const int w    = tid >> 5;
    const int lane = tid & 31;
    const int wm = w & 1;
    const int wn = w >> 1;

    const int lt = lane >> 3, lr = lane & 7;
    const uint32_t aLane = (uint32_t)(((lt & 1) * 8 + lr) * LROW + (lt >> 1) * 16);
    const uint32_t bLane = (uint32_t)(((lt >> 1) * 8 + lr) * LROW + (lt & 1) * 16);

    float acc[2][8][4];
#pragma unroll
    for (int i = 0; i < 2; i++)
#pragma unroll
        for (int j = 0; j < 8; j++)
#pragma unroll
            for (int q = 0; q < 4; q++) acc[i][j][q] = 0.f;

    for (int c = 0; c < 4; c++) {
        const int k0 = c * BKQ;
#pragma unroll
        for (int i = 0; i < 2; i++) {
            int e = tid + i * 256;
            int row = e >> 3, kc = e & 7;
            size_t go = (size_t)(bm + row) * K + k0 + kc * 8;
            uint32_t so = sb + row * LROW + kc * 16;
            cp16(so + G2_AH, Ah + go);
            cp16(so + G2_AL, Al + go);
        }
#pragma unroll
        for (int i = 0; i < 8; i++) {
            int e = tid + i * 256;
            int row = e >> 3, kc = e & 7;
            size_t go = (size_t)(nb + row) * K + k0 + kc * 8;
            uint32_t so = sb + row * LROW + kc * 16;
            cp16(so + G2_BH, Bh + go);
            cp16(so + G2_BL, Bl + go);
        }
        CP_COMMIT();
        CP_WAIT0();
        __syncthreads();

        const uint32_t aBase = sb + G2_AH + (wm * 32) * LROW + aLane;
        const uint32_t bBase = sb + G2_BH + (wn * 64) * LROW + bLane;
#pragma unroll
        for (int kk = 0; kk < 4; kk++) {
            uint32_t ah[2][4], al[2][4];
#pragma unroll
            for (int mi = 0; mi < 2; mi++) {
                uint32_t a0 = aBase + mi * (16 * LROW) + kk * 32;
                ldm_x4(ah[mi], a0);
                ldm_x4(al[mi], a0 + (G2_AL - G2_AH));
            }
#pragma unroll
            for (int g = 0; g < 4; g++) {
                uint32_t bh[4], bl[4];
                uint32_t b0 = bBase + g * (16 * LROW) + kk * 32;
                ldm_x4(bh, b0);
                ldm_x4(bl, b0 + (G2_BL - G2_BH));
#pragma unroll
                for (int mi = 0; mi < 2; mi++) {
                    mma16816(acc[mi][2 * g],     ah[mi], bh);
                    mma16816(acc[mi][2 * g],     ah[mi], bl);
                    mma16816(acc[mi][2 * g],     al[mi], bh);
                    mma16816(acc[mi][2 * g + 1], ah[mi], bh + 2);
                    mma16816(acc[mi][2 * g + 1], ah[mi], bl + 2);
                    mma16816(acc[mi][2 * g + 1], al[mi], bh + 2);
                }
            }
        }
        __syncthreads();
    }

    float* Cs = (float*)smem;
    const int g4 = lane >> 2, tig = lane & 3;
#pragma unroll
    for (int mi = 0; mi < 2; mi++)
#pragma unroll
        for (int nj = 0; nj < 8; nj++) {
            int row = wm * 32 + mi * 16 + g4;
            int col = wn * 64 + nj * 8 + tig * 2;
            *(float2*)(Cs + row * LDCE + col)       = make_float2(acc[mi][nj][0], acc[mi][nj][1]);
            *(float2*)(Cs + (row + 8) * LDCE + col) = make_float2(acc[mi][nj][2], acc[mi][nj][3]);
        }
    __syncthreads();

    const int r = tid >> 2;
    const int ch = (tid & 3) * 64;
    float* crow = Cs + r * LDCE + ch;
    float s = 0.f, sq = 0.f;
#pragma unroll
    for (int g = 0; g < 16; g++) {
        float4 v = *(const float4*)(crow + g * 4);
        v.x = gelu_exact(v.x); v.y = gelu_exact(v.y);
        v.z = gelu_exact(v.z); v.w = gelu_exact(v.w);
        *(float4*)(crow + g * 4) = v;
        s  += v.x + v.y + v.z + v.w;
        sq += v.x * v.x + v.y * v.y + v.z * v.z + v.w * v.w;
    }
    s  += __shfl_xor_sync(0xffffffffu, s, 1);
    sq += __shfl_xor_sync(0xffffffffu, sq, 1);
    s  += __shfl_xor_sync(0xffffffffu, s, 2);
    sq += __shfl_xor_sync(0xffffffffu, sq, 2);
    if ((tid & 3) == 0) part[r] = make_float2(s, sq);

    cg::cluster_group cluster = cg::this_cluster();
    cluster.sync();
    float S = 0.f, SQ = 0.f;
#pragma unroll
    for (unsigned rk = 0; rk < 4; rk++) {
        const float2* pp = cluster.map_shared_rank(part, rk);
        float2 p = pp[r];
        S += p.x; SQ += p.y;
    }
    const float mean = S * (1.f / DMOD);
    const float var  = SQ * (1.f / DMOD) - mean * mean;
    const float rstd = rsqrtf(var + 1e-5f);

    float* po = out + (size_t)(bm + r) * DMOD + nb + ch;
    const float* gm = gamma + nb + ch;
    const float* bt = beta + nb + ch;
#pragma unroll
    for (int g = 0; g < 16; g++) {
        float4 v  = *(const float4*)(crow + g * 4);
        float4 gg = *(const float4*)(gm + g * 4);
        float4 bb = *(const float4*)(bt + g * 4);
        float4 o;
        o.x = (v.x - mean) * rstd * gg.x + bb.x;
        o.y = (v.y - mean) * rstd * gg.y + bb.y;
        o.z = (v.z - mean) * rstd * gg.z + bb.z;
        o.w = (v.w - mean) * rstd * gg.w + bb.w;
        *(float4*)(po + g * 4) = o;
    }
    cluster.sync();
}

// ---------------------------------------------------------------------------
// kernel_launch — fork prep onto a side stream to overlap with GEMM1.
// ---------------------------------------------------------------------------
extern "C" void kernel_launch(void* const* d_in, const int* in_sizes, int n_in,
                              void* d_out, int out_size)
{
    const float* x     = (const float*)d_in[0];
    const float* A     = (const float*)d_in[1];
    const float* Bmat  = (const float*)d_in[2];
    const float* C     = (const float*)d_in[3];
    const float* gamma = (const float*)d_in[4];
    const float* beta  = (const float*)d_in[5];
    float* out = (float*)d_out;

    __nv_bfloat16 *wh0, *wl0, *wh1, *wl1, *Bh, *Bl, *Ch, *Cl, *Ph, *Pl, *P2h;
    float *P;
    cudaGetSymbolAddress((void**)&wh0, g_wh);   wh1 = wh0 + (size_t)MROWS * SDIM;
    cudaGetSymbolAddress((void**)&wl0, g_wl);   wl1 = wl0 + (size_t)MROWS * SDIM;
    cudaGetSymbolAddress((void**)&Bh, g_Bh);
    cudaGetSymbolAddress((void**)&Bl, g_Bl);
    cudaGetSymbolAddress((void**)&Ch, g_Ch);
    cudaGetSymbolAddress((void**)&Cl, g_Cl);
    cudaGetSymbolAddress((void**)&P,  g_P);
    cudaGetSymbolAddress((void**)&Ph, g_Ph);
    cudaGetSymbolAddress((void**)&Pl, g_Pl);
    cudaGetSymbolAddress((void**)&P2h, g_P2h);

    cudaFuncSetAttribute((void*)gemm1,    cudaFuncAttributeMaxDynamicSharedMemorySize, SMEM_SZ);
    cudaFuncSetAttribute((void*)scan1,    cudaFuncAttributeMaxDynamicSharedMemorySize, S1_SMEM);
    cudaFuncSetAttribute((void*)scan3,    cudaFuncAttributeMaxDynamicSharedMemorySize, S3_SMEM);
    cudaFuncSetAttribute((void*)gemm2_ln, cudaFuncAttributeMaxDynamicSharedMemorySize, G2_SMEM);

    // ---- fork: side stream runs C/A-prep + matrix powers concurrently ----
    cudaEventRecord(g_ss.eFork, 0);
    cudaStreamWaitEvent(g_ss.s2, g_ss.eFork, 0);

    const int n2 = (DMOD * SDIM + SDIM * SDIM + 2 * SDIM * SDIM) / 4;
    prep2<<<(n2 + 255) / 256, 256, 0, g_ss.s2>>>(C, A, Ch, Cl, Ph, Pl, P);
    const dim3 skgrid(4, 4, 8);
    matsq_sk<<<skgrid, 256, 0, g_ss.s2>>>(A, P);                  // A^2
    matsq_sk<<<skgrid, 256, 0, g_ss.s2>>>(P, P + SDIM * SDIM);    // A^4
    conv_hi<<<2 * SDIM * SDIM / 4 / 256, 256, 0, g_ss.s2>>>(P, P2h, 2 * SDIM * SDIM / 4);
    cudaEventRecord(g_ss.eJoin, g_ss.s2);

    // ---- main stream: B split, GEMM1 ----
    bsplit<<<SDIM * DMOD / 4 / 256, 256>>>(Bmat, Bh, Bl);
    gemm1<<<dim3(1, MROWS / 128), NTHR, SMEM_SZ>>>(x, Bh, Bl, wh0, wl0, DMOD);

    // ---- join ----
    cudaStreamWaitEvent(0, g_ss.eJoin, 0);

    // ---- scan: d=1 (2-term, BM=64, occ>=2), then fused d=2+4 ----
    scan1<<<dim3(1, MROWS / 64), 256, S1_SMEM>>>(wh0, wl0, Ph, wh1, wl1);
    scan3<<<dim3(1, MROWS / 64), 256, S3_SMEM>>>(
        wh1, wl1, P2h, P2h + SDIM * SDIM, wh0, wl0);

    // ---- GEMM2 + GELU + LayerNorm fused (BM=64, occ 2, cluster over N) ----
    gemm2_ln<<<dim3(DMOD / 256, MROWS / 64), 256, G2_SMEM>>>(
        wh0, wl0, Ch, Cl, gamma, beta, out);
}